// round 12
// baseline (speedup 1.0000x reference)
#include <cuda_runtime.h>
#include <cuda_fp16.h>
#include <cstdint>

// ============================================================
// TopKRouter dual-pipe v2 (register-safe):
//   96 tok/CTA via HMMA fp16 2-split + 32 tok/CTA via fp32 f32x2
//   logits = x @ W^T + b ; top-2 ; softmax(top2)
// 416 thr (157-reg ceiling):
//   w0-5 : HMMA consumers (m16n64)   w6-7 : fp32 consumers
//   w8-11: HMMA producers            w12  : fp32 producer (pure cp)
// Independent rings: H 3x40KB, F 2x26112B. grid = 128.
// ============================================================

#define D_DIM  2048
#define NEXP   64
#define MH     96
#define MF     32
#define NCH    32
#define NTHREADS 416

// ring H (stage-relative): Ah0 0 | Ah1 12288 | Wh0 24576 | Wh1 32768
#define AH1r   12288
#define WH0r   24576
#define HSTGSZ 40960
#define HSTG(s) (1024 + (s) * HSTGSZ)
// ring F (stage-relative): X 0 (32x272) | W 8704 (64x272)
#define FWr    8704
#define FSTGSZ 26112
#define FSTG(s) (123904 + (s) * FSTGSZ)
#define SMEM_TOTAL 176128
#define LGS    65
#define SW16(row, c) ((row) * 128 + ((((c) ^ ((row) & 7))) << 4))
// fp32 ring swizzle: additive column rotation -> conflict-free for
// rows 4 apart (x) AND 8 apart (w)
#define FCOL(row, c) ((((c) + (row) + ((row) >> 3)) & 15) << 4)
#define FSW(row, c) ((row) * 272 + FCOL(row, c))

__device__ __align__(16) __half w0g[NEXP * D_DIM];
__device__ __align__(16) __half w1g[NEXP * D_DIM];

__global__ void wconv(const float* __restrict__ W) {
    int i = blockIdx.x * blockDim.x + threadIdx.x;
    float w = W[i];
    __half h0 = __float2half_rn(w);
    float  r  = w - __half2float(h0);
    w0g[i] = h0;
    w1g[i] = __float2half_rn(r * 2048.0f);
}

// ---------------- asm helpers ----------------
__device__ __forceinline__ uint32_t smem_u32(const void* p) {
    uint32_t a;
    asm("{ .reg .u64 t; cvta.to.shared.u64 t, %1; cvt.u32.u64 %0, t; }"
        : "=r"(a) : "l"(p));
    return a;
}
__device__ __forceinline__ void ldsm4(uint32_t* r, uint32_t addr) {
    asm volatile("ldmatrix.sync.aligned.m8n8.x4.shared.b16 {%0,%1,%2,%3}, [%4];"
                 : "=r"(r[0]), "=r"(r[1]), "=r"(r[2]), "=r"(r[3]) : "r"(addr));
}
__device__ __forceinline__ void mma16816(float* d, const uint32_t* a, const uint32_t* b) {
    asm volatile("mma.sync.aligned.m16n8k16.row.col.f32.f16.f16.f32 "
                 "{%0,%1,%2,%3}, {%4,%5,%6,%7}, {%8,%9}, {%0,%1,%2,%3};"
                 : "+f"(d[0]), "+f"(d[1]), "+f"(d[2]), "+f"(d[3])
                 : "r"(a[0]), "r"(a[1]), "r"(a[2]), "r"(a[3]), "r"(b[0]), "r"(b[1]));
}
__device__ __forceinline__ void cp16(uint32_t saddr, const void* gaddr) {
    asm volatile("cp.async.cg.shared.global [%0], [%1], 16;" :: "r"(saddr), "l"(gaddr));
}
#define MBAR_INIT(a, c) \
    asm volatile("mbarrier.init.shared.b64 [%0], %1;" :: "r"(a), "r"(c) : "memory")
#define MBAR_ARRIVE(a) \
    asm volatile("mbarrier.arrive.release.cta.shared::cta.b64 _, [%0];" :: "r"(a) : "memory")
#define CP_MBAR_ARRIVE(a) \
    asm volatile("cp.async.mbarrier.arrive.noinc.shared.b64 [%0];" :: "r"(a) : "memory")
#define MBAR_WAIT(addr, ph) do { \
    asm volatile("{\n\t.reg .pred P;\n\tWLP_%=:\n\t" \
        "mbarrier.try_wait.parity.acquire.cta.shared::cta.b64 P, [%0], %1, 0x989680;\n\t" \
        "@!P bra WLP_%=;\n\t}" :: "r"(addr), "r"(ph) : "memory"); \
} while (0)
#define STS128(addr, v) \
    asm volatile("st.shared.v4.b32 [%0], {%1,%2,%3,%4};" \
                 :: "r"(addr), "r"((v).x), "r"((v).y), "r"((v).z), "r"((v).w) : "memory")
#define FMA2(acc, a, b) \
    asm("fma.rn.f32x2 %0, %1, %2, %0;" : "+l"(acc) : "l"(a), "l"(b))

__device__ __forceinline__ uint32_t cvt2(float u, float v, uint32_t& h1) {
    __half2 a = __float22half2_rn(make_float2(u, v));
    float2 f  = __half22float2(a);
    __half2 r = __float22half2_rn(make_float2(u - f.x, v - f.y));
    h1 = *reinterpret_cast<uint32_t*>(&r);
    return *reinterpret_cast<uint32_t*>(&a);
}

// ---------------- main kernel ----------------
__global__ __launch_bounds__(NTHREADS, 1)
void router_main(const float* __restrict__ x, const float* __restrict__ W,
                 const float* __restrict__ b, float* __restrict__ out, int n_tokens)
{
    extern __shared__ __align__(1024) char smem[];
    const uint32_t sb = smem_u32(smem);
    const int tid  = threadIdx.x;
    const int lane = tid & 31;
    const int blk  = blockIdx.x;
    const int tok0h = blk * MH;
    const int tok0f = gridDim.x * MH + blk * MF;

    // mbars: H full sb+512+16s / empty +8 (s<3) ; F full sb+576+16s / +8 (s<2)
    if (tid == 0) {
#pragma unroll
        for (int s = 0; s < 3; s++) {
            MBAR_INIT(sb + 512 + s * 16, 256);       // H full: 128 arr + 128 cp
            MBAR_INIT(sb + 512 + s * 16 + 8, 192);   // H empty: 6 warps
        }
#pragma unroll
        for (int s = 0; s < 2; s++) {
            MBAR_INIT(sb + 576 + s * 16, 64);        // F full: 32 arr + 32 cp
            MBAR_INIT(sb + 576 + s * 16 + 8, 64);    // F empty: 2 warps
        }
    }
    if (tid < NEXP) reinterpret_cast<float*>(smem)[tid] = b[tid];
    __syncthreads();

    // =================== HMMA PRODUCERS (warps 8-11) ===================
    if (tid >= 256 && tid < 384) {
        const int pt   = tid - 256;        // 0..127
        const int wrow = pt & 63;
        const int wsp  = pt >> 6;
        const char* wg = reinterpret_cast<const char*>(wsp ? w1g : w0g)
                         + wrow * (D_DIM * 2);
        const uint32_t wdst = WH0r + wsp * 8192;
        uint32_t wsw[8];
#pragma unroll
        for (int c = 0; c < 8; c++) wsw[c] = SW16(wrow, c);

        const bool doX = (pt < MH);
        const float4* xp = reinterpret_cast<const float4*>(x)
                           + (size_t)(tok0h + (doX ? pt : 0)) * (D_DIM / 4);
        uint32_t asw[8];
#pragma unroll
        for (int q = 0; q < 8; q++) asw[q] = SW16(pt, q);

        float4 xv[16];
        if (doX) {
#pragma unroll
            for (int i = 0; i < 16; i++) xv[i] = xp[i];
        }

        int s = 0, ph = 1;
        for (int ch = 0; ch < NCH; ch++) {
            const uint32_t fullb  = sb + 512 + s * 16;
            const uint32_t emptyb = fullb + 8;
            MBAR_WAIT(emptyb, ph);
            const uint32_t stg = sb + HSTG(s);

#pragma unroll
            for (int c = 0; c < 8; c++)
                cp16(stg + wdst + wsw[c], wg + ch * 128 + c * 16);

            if (doX) {
#pragma unroll
                for (int q = 0; q < 8; q++) {
                    float4 a = xv[2 * q], c = xv[2 * q + 1];
                    uint4 h0q, h1q;
                    h0q.x = cvt2(a.x, a.y, h1q.x);
                    h0q.y = cvt2(a.z, a.w, h1q.y);
                    h0q.z = cvt2(c.x, c.y, h1q.z);
                    h0q.w = cvt2(c.z, c.w, h1q.w);
                    STS128(stg + asw[q], h0q);
                    STS128(stg + AH1r + asw[q], h1q);
                }
            }
            CP_MBAR_ARRIVE(fullb);
            MBAR_ARRIVE(fullb);

            if (doX && ch + 1 < NCH) {
#pragma unroll
                for (int i = 0; i < 16; i++) xv[i] = xp[(ch + 1) * 16 + i];
            }
            if (++s == 3) { s = 0; ph ^= 1; }
        }
        return;
    }

    // =================== FP32 PRODUCER (warp 12, pure cp.async) ===================
    if (tid >= 384) {
        const int t = tid - 384;           // 0..31
        const char* wf = reinterpret_cast<const char*>(W);
        const char* xf = reinterpret_cast<const char*>(x)
                         + (size_t)tok0f * (D_DIM * 4);

        int s = 0, ph = 1;
        for (int ch = 0; ch < NCH; ch++) {
            const uint32_t fullb  = sb + 576 + s * 16;
            const uint32_t emptyb = fullb + 8;
            MBAR_WAIT(emptyb, ph);
            const uint32_t stg = sb + FSTG(s);

            // W fp32: 64 rows x 256B = 1024 cp16; idx = t + 32*i
#pragma unroll
            for (int i = 0; i < 32; i++) {
                int idx = t + 32 * i;
                int row = idx >> 4, c = idx & 15;
                cp16(stg + FWr + FSW(row, c),
                     wf + (size_t)row * (D_DIM * 4) + ch * 256 + c * 16);
            }
            // x fp32: 32 rows x 256B = 512 cp16
#pragma unroll
            for (int i = 0; i < 16; i++) {
                int idx = t + 32 * i;
                int row = idx >> 4, c = idx & 15;
                cp16(stg + FSW(row, c),
                     xf + (size_t)row * (D_DIM * 4) + ch * 256 + c * 16);
            }
            CP_MBAR_ARRIVE(fullb);
            MBAR_ARRIVE(fullb);
            if (++s == 2) { s = 0; ph ^= 1; }
        }
        return;
    }

    float* lg = reinterpret_cast<float*>(smem + 1024);

    if (tid < 192) {
        // ============ HMMA CONSUMERS (warps 0-5): m16n64 each ============
        const int wid = tid >> 5;
        const int m0  = wid * 16;

        float acc0[8][4], acc1[8][4];
#pragma unroll
        for (int ng = 0; ng < 8; ng++)
#pragma unroll
            for (int q = 0; q < 4; q++) { acc0[ng][q] = 0.f; acc1[ng][q] = 0.f; }

        const int rowA  = m0 + (lane & 15);
        const int cAoff = lane >> 4;
        const int rowBb = (lane & 7) + ((lane >> 4) << 3);
        const int cBoff = (lane >> 3) & 1;

        int s = 0, ph = 0;
        for (int ch = 0; ch < NCH; ch++) {
            const uint32_t fullb  = sb + 512 + s * 16;
            const uint32_t emptyb = fullb + 8;
            MBAR_WAIT(fullb, ph);
            const uint32_t stg = sb + HSTG(s);

#pragma unroll
            for (int kk = 0; kk < 4; kk++) {
                uint32_t a0f[4], a1f[4], b0f[4][4], b1f[4][4];
                const int cA = kk * 2 + cAoff;
                const int cB = kk * 2 + cBoff;
                uint32_t ad = stg + SW16(rowA, cA);
                ldsm4(a0f, ad);
                ldsm4(a1f, ad + AH1r);
#pragma unroll
                for (int j = 0; j < 4; j++) {
                    uint32_t bd = stg + WH0r + SW16(16 * j + rowBb, cB);
                    ldsm4(b0f[j], bd);
                    ldsm4(b1f[j], bd + 8192);
                }
                if (kk == 3) MBAR_ARRIVE(emptyb);
#pragma unroll
                for (int ng = 0; ng < 8; ng++)
                    mma16816(acc0[ng], a0f, &b0f[ng >> 1][(ng & 1) * 2]);
#pragma unroll
                for (int ng = 0; ng < 8; ng++)
                    mma16816(acc0[ng], a1f, &b0f[ng >> 1][(ng & 1) * 2]);
#pragma unroll
                for (int ng = 0; ng < 8; ng++)
                    mma16816(acc1[ng], a0f, &b1f[ng >> 1][(ng & 1) * 2]);
            }
            if (++s == 3) { s = 0; ph ^= 1; }
        }

        asm volatile("bar.sync 1, 256;" ::: "memory");   // all ring reads done

        const float S = 4.8828125e-4f;  // 2^-11
#pragma unroll
        for (int ng = 0; ng < 8; ng++) {
            int row = m0 + (lane >> 2);
            int col = ng * 8 + 2 * (lane & 3);
            lg[row * LGS + col]           = acc0[ng][0] + S * acc1[ng][0];
            lg[row * LGS + col + 1]       = acc0[ng][1] + S * acc1[ng][1];
            lg[(row + 8) * LGS + col]     = acc0[ng][2] + S * acc1[ng][2];
            lg[(row + 8) * LGS + col + 1] = acc0[ng][3] + S * acc1[ng][3];
        }
    } else {
        // ============ FP32 CONSUMERS (warps 6-7): 32 tok x 64 exp ============
        const int ft   = tid - 192;    // 0..63
        const int tokg = ft >> 3;      // tokens 4*tokg..+3 (0..7)
        const int eg   = ft & 7;       // experts 8*eg..+7

        int xrot[4], wrot[8];
        uint32_t xbase[4], wbase[8];
#pragma unroll
        for (int i = 0; i < 4; i++) {
            int r = 4 * tokg + i;
            xrot[i]  = (r + (r >> 3)) & 15;
            xbase[i] = r * 272;
        }
#pragma unroll
        for (int j = 0; j < 8; j++) {
            int r = 8 * eg + j;
            wrot[j]  = (r + (r >> 3)) & 15;
            wbase[j] = FWr + r * 272;
        }

        unsigned long long acc[4][8];
#pragma unroll
        for (int i = 0; i < 4; i++)
#pragma unroll
            for (int j = 0; j < 8; j++) acc[i][j] = 0ull;

        int s = 0, ph = 0;
        for (int ch = 0; ch < NCH; ch++) {
            const uint32_t fullb  = sb + 576 + s * 16;
            const uint32_t emptyb = fullb + 8;
            MBAR_WAIT(fullb, ph);
            const char* stg = smem + FSTG(s);

#pragma unroll 4
            for (int k4 = 0; k4 < 16; k4++) {
                ulonglong2 xv4[4], wv4[8];
#pragma unroll
                for (int i = 0; i < 4; i++)
                    xv4[i] = *reinterpret_cast<const ulonglong2*>(
                        stg + xbase[i] + (((k4 + xrot[i]) & 15) << 4));
#pragma unroll
                for (int j = 0; j < 8; j++)
                    wv4[j] = *reinterpret_cast<const ulonglong2*>(
                        stg + wbase[j] + (((k4 + wrot[j]) & 15) << 4));
#pragma unroll
                for (int i = 0; i < 4; i++)
#pragma unroll
                    for (int j = 0; j < 8; j++) {
                        FMA2(acc[i][j], xv4[i].x, wv4[j].x);
                        FMA2(acc[i][j], xv4[i].y, wv4[j].y);
                    }
            }
            MBAR_ARRIVE(emptyb);
            if (++s == 2) { s = 0; ph ^= 1; }
        }

        asm volatile("bar.sync 1, 256;" ::: "memory");

#pragma unroll
        for (int i = 0; i < 4; i++)
#pragma unroll
            for (int j = 0; j < 8; j++) {
                float2 f2 = *reinterpret_cast<float2*>(&acc[i][j]);
                lg[(MH + 4 * tokg + i) * LGS + 8 * eg + j] = f2.x + f2.y;
            }
    }

    asm volatile("bar.sync 1, 256;" ::: "memory");

    // ---- top-2 + softmax: rows 0-95 HMMA tokens, 96-127 fp32 tokens ----
    if (tid < MH + MF) {
        const float* row = &lg[tid * LGS];
        const float* bs  = reinterpret_cast<const float*>(smem);
        float v1 = -3.402823466e+38f, v2 = -3.402823466e+38f;
        int i1 = 0, i2 = 0;
#pragma unroll
        for (int e = 0; e < NEXP; e++) {
            float v = row[e] + bs[e];
            if (v > v1)      { v2 = v1; i2 = i1; v1 = v; i1 = e; }
            else if (v > v2) { v2 = v;  i2 = e; }
        }
        float e2  = expf(v2 - v1);
        float inv = 1.0f / (1.0f + e2);
        const int g = (tid < MH) ? (tok0h + tid) : (tok0f + tid - MH);
        out[2 * g + 0] = inv;
        out[2 * g + 1] = e2 * inv;
        out[2 * n_tokens + 2 * g + 0] = (float)i1;
        out[2 * n_tokens + 2 * g + 1] = (float)i2;
    }
}

// ---------------- launch ----------------
extern "C" void kernel_launch(void* const* d_in, const int* in_sizes, int n_in,
                              void* d_out, int out_size)
{
    const float* x = (const float*)d_in[0];
    const float* W = (const float*)d_in[1];
    const float* b = (const float*)d_in[2];
    float* out = (float*)d_out;

    const int n_tokens = in_sizes[0] / D_DIM;       // 16384
    const int grid = n_tokens / (MH + MF);          // 128

    cudaFuncSetAttribute(router_main, cudaFuncAttributeMaxDynamicSharedMemorySize, SMEM_TOTAL);

    wconv<<<NEXP * D_DIM / 256, 256>>>(W);
    router_main<<<grid, NTHREADS, SMEM_TOTAL>>>(x, W, b, out, n_tokens);
}

// round 14
// speedup vs baseline: 2.2651x; 2.2651x over previous
#include <cuda_runtime.h>
#include <cuda_fp16.h>
#include <cstdint>

// ============================================================
// TopKRouter, warp-specialized HMMA fp16 2-split pipeline v6:
//   logits = x @ W^T + b ; top-2 ; softmax(top2)
// M_CTA=112, grid=147 (covers 147/148 SMs, 0.875x work/SM vs R7)
// 352 threads: warps 0-6 MMA consumers (m16n64 each),
//              warps 7-10 producers. 4-stage smem ring.
// ============================================================

#define D_DIM  2048
#define NEXP   64
#define M_CTA  112
#define NCH    32
#define NSTG   4
#define NTHREADS 352

// stage: A-h0 [0,14336) | A-h1 [14336,28672) | W-w0 [28672,36864) | W-w1 [36864,45056)
#define AB       14336
#define WB       8192
#define WOFF     28672
#define STGSZ    45056
#define STG(s)   (1024 + (s) * STGSZ)
#define SMEM_TOTAL (1024 + NSTG * STGSZ)   // 181248
#define LG_OFF   1024
#define LGS      65
#define SW16(row, c) ((row) * 128 + ((((c) ^ ((row) & 7))) << 4))

__device__ __align__(16) __half w0g[NEXP * D_DIM];
__device__ __align__(16) __half w1g[NEXP * D_DIM];

__global__ void wconv(const float* __restrict__ W) {
    int i = blockIdx.x * blockDim.x + threadIdx.x;
    float w = W[i];
    __half h0 = __float2half_rn(w);
    float  r  = w - __half2float(h0);
    w0g[i] = h0;
    w1g[i] = __float2half_rn(r * 2048.0f);
}

// ---------------- asm helpers ----------------
__device__ __forceinline__ uint32_t smem_u32(const void* p) {
    uint32_t a;
    asm("{ .reg .u64 t; cvta.to.shared.u64 t, %1; cvt.u32.u64 %0, t; }"
        : "=r"(a) : "l"(p));
    return a;
}
__device__ __forceinline__ void ldsm4(uint32_t* r, uint32_t addr) {
    asm volatile("ldmatrix.sync.aligned.m8n8.x4.shared.b16 {%0,%1,%2,%3}, [%4];"
                 : "=r"(r[0]), "=r"(r[1]), "=r"(r[2]), "=r"(r[3]) : "r"(addr));
}
__device__ __forceinline__ void mma16816(float* d, const uint32_t* a, const uint32_t* b) {
    asm volatile("mma.sync.aligned.m16n8k16.row.col.f32.f16.f16.f32 "
                 "{%0,%1,%2,%3}, {%4,%5,%6,%7}, {%8,%9}, {%0,%1,%2,%3};"
                 : "+f"(d[0]), "+f"(d[1]), "+f"(d[2]), "+f"(d[3])
                 : "r"(a[0]), "r"(a[1]), "r"(a[2]), "r"(a[3]), "r"(b[0]), "r"(b[1]));
}
__device__ __forceinline__ void cp16(uint32_t saddr, const void* gaddr) {
    asm volatile("cp.async.cg.shared.global [%0], [%1], 16;" :: "r"(saddr), "l"(gaddr));
}
#define MBAR_INIT(a, c) \
    asm volatile("mbarrier.init.shared.b64 [%0], %1;" :: "r"(a), "r"(c) : "memory")
#define MBAR_ARRIVE(a) \
    asm volatile("mbarrier.arrive.release.cta.shared::cta.b64 _, [%0];" :: "r"(a) : "memory")
// .noinc is load-bearing (default raises pend-count -> deadlock)
#define CP_MBAR_ARRIVE(a) \
    asm volatile("cp.async.mbarrier.arrive.noinc.shared.b64 [%0];" :: "r"(a) : "memory")
#define MBAR_WAIT(addr, ph) do { \
    asm volatile("{\n\t.reg .pred P;\n\tWLP_%=:\n\t" \
        "mbarrier.try_wait.parity.acquire.cta.shared::cta.b64 P, [%0], %1, 0x989680;\n\t" \
        "@!P bra WLP_%=;\n\t}" :: "r"(addr), "r"(ph) : "memory"); \
} while (0)
#define STS128(addr, v) \
    asm volatile("st.shared.v4.b32 [%0], {%1,%2,%3,%4};" \
                 :: "r"(addr), "r"((v).x), "r"((v).y), "r"((v).z), "r"((v).w) : "memory")

__device__ __forceinline__ uint32_t cvt2(float u, float v, uint32_t& h1) {
    __half2 a = __float22half2_rn(make_float2(u, v));
    float2 f  = __half22float2(a);
    __half2 r = __float22half2_rn(make_float2(u - f.x, v - f.y));
    h1 = *reinterpret_cast<uint32_t*>(&r);
    return *reinterpret_cast<uint32_t*>(&a);
}

// ---------------- main kernel ----------------
__global__ __launch_bounds__(NTHREADS)
void router_main(const float* __restrict__ x, const float* __restrict__ b,
                 float* __restrict__ out, int n_tokens)
{
    extern __shared__ __align__(1024) char smem[];
    const uint32_t sb = smem_u32(smem);
    const int tid  = threadIdx.x;
    const int lane = tid & 31;
    const int tok0 = blockIdx.x * M_CTA;

    if (tid == 0) {
#pragma unroll
        for (int s = 0; s < NSTG; s++) {
            MBAR_INIT(sb + 512 + s * 16, 256);      // 128 STS-arr + 128 cp-arr
            MBAR_INIT(sb + 512 + s * 16 + 8, 224);  // 224 consumer arrivals
        }
    }
    if (tid < NEXP) reinterpret_cast<float*>(smem)[tid] = b[tid];
    __syncthreads();

    if (tid >= 224) {
        // ================= PRODUCER (warps 7-10, 128 threads) =================
        const int pt   = tid - 224;        // 0..127
        const int wrow = pt & 63;
        const int wsp  = pt >> 6;
        const char* wg = reinterpret_cast<const char*>(wsp ? w1g : w0g)
                         + wrow * (D_DIM * 2);
        const uint32_t wdst = WOFF + wsp * WB;
        uint32_t wsw[8];
#pragma unroll
        for (int c = 0; c < 8; c++) wsw[c] = SW16(wrow, c);

        const bool doX = (pt < M_CTA);
        // clamp OOB token rows (last CTA) to a valid row; results discarded
        int xrow = tok0 + pt;
        if (xrow >= n_tokens) xrow = n_tokens - 1;
        const float4* xp = reinterpret_cast<const float4*>(x)
                           + (size_t)xrow * (D_DIM / 4);
        uint32_t asw[8];
#pragma unroll
        for (int q = 0; q < 8; q++) asw[q] = SW16(pt, q);

        float4 xv[16];
        if (doX) {
#pragma unroll
            for (int i = 0; i < 16; i++) xv[i] = xp[i];
        }

        int s = 0, ph = 1;
        for (int ch = 0; ch < NCH; ch++) {
            const uint32_t fullb  = sb + 512 + s * 16;
            const uint32_t emptyb = fullb + 8;
            MBAR_WAIT(emptyb, ph);
            const uint32_t stg = sb + STG(s);

#pragma unroll
            for (int c = 0; c < 8; c++)
                cp16(stg + wdst + wsw[c], wg + ch * 128 + c * 16);

            if (doX) {
#pragma unroll
                for (int q = 0; q < 8; q++) {
                    float4 a = xv[2 * q], c = xv[2 * q + 1];
                    uint4 h0q, h1q;
                    h0q.x = cvt2(a.x, a.y, h1q.x);
                    h0q.y = cvt2(a.z, a.w, h1q.y);
                    h0q.z = cvt2(c.x, c.y, h1q.z);
                    h0q.w = cvt2(c.z, c.w, h1q.w);
                    STS128(stg + asw[q], h0q);
                    STS128(stg + AB + asw[q], h1q);
                }
            }
            CP_MBAR_ARRIVE(fullb);
            MBAR_ARRIVE(fullb);

            if (doX && ch + 1 < NCH) {
#pragma unroll
                for (int i = 0; i < 16; i++) xv[i] = xp[(ch + 1) * 16 + i];
            }
            if (++s == NSTG) { s = 0; ph ^= 1; }
        }
        return;
    }

    // ================= CONSUMER (warps 0-6): m16n64 each =================
    const int wid = tid >> 5;
    const int m0  = wid * 16;

    float acc0[8][4], acc1[8][4];
#pragma unroll
    for (int ng = 0; ng < 8; ng++)
#pragma unroll
        for (int q = 0; q < 4; q++) { acc0[ng][q] = 0.f; acc1[ng][q] = 0.f; }

    const int rowA  = m0 + (lane & 15);
    const int cAoff = lane >> 4;
    const int rowBb = (lane & 7) + ((lane >> 4) << 3);
    const int cBoff = (lane >> 3) & 1;

    int s = 0, ph = 0;
    for (int ch = 0; ch < NCH; ch++) {
        const uint32_t fullb  = sb + 512 + s * 16;
        const uint32_t emptyb = fullb + 8;
        MBAR_WAIT(fullb, ph);
        const uint32_t stg = sb + STG(s);

#pragma unroll
        for (int kk = 0; kk < 4; kk++) {
            uint32_t a0f[4], a1f[4], b0f[4][4], b1f[4][4];
            const int cA = kk * 2 + cAoff;
            const int cB = kk * 2 + cBoff;
            uint32_t ad = stg + SW16(rowA, cA);
            ldsm4(a0f, ad);
            ldsm4(a1f, ad + AB);
#pragma unroll
            for (int j = 0; j < 4; j++) {
                uint32_t bd = stg + WOFF + SW16(16 * j + rowBb, cB);
                ldsm4(b0f[j], bd);
                ldsm4(b1f[j], bd + WB);
            }
            if (kk == 3) MBAR_ARRIVE(emptyb);
            // pass-major order: acc reuse distance 8 -> no RAW stalls
#pragma unroll
            for (int ng = 0; ng < 8; ng++)
                mma16816(acc0[ng], a0f, &b0f[ng >> 1][(ng & 1) * 2]);
#pragma unroll
            for (int ng = 0; ng < 8; ng++)
                mma16816(acc0[ng], a1f, &b0f[ng >> 1][(ng & 1) * 2]);
#pragma unroll
            for (int ng = 0; ng < 8; ng++)
                mma16816(acc1[ng], a0f, &b1f[ng >> 1][(ng & 1) * 2]);
        }
        if (++s == NSTG) { s = 0; ph ^= 1; }
    }

    // consumers must finish reading stage 0 before logits overwrite it
    asm volatile("bar.sync 1, 224;" ::: "memory");

    // ---- epilogue: combine splits -> logits smem ----
    float* lg = reinterpret_cast<float*>(smem + LG_OFF);
    const float S = 4.8828125e-4f;  // 2^-11
#pragma unroll
    for (int ng = 0; ng < 8; ng++) {
        int row = m0 + (lane >> 2);
        int col = ng * 8 + 2 * (lane & 3);
        lg[row * LGS + col]           = acc0[ng][0] + S * acc1[ng][0];
        lg[row * LGS + col + 1]       = acc0[ng][1] + S * acc1[ng][1];
        lg[(row + 8) * LGS + col]     = acc0[ng][2] + S * acc1[ng][2];
        lg[(row + 8) * LGS + col + 1] = acc0[ng][3] + S * acc1[ng][3];
    }
    asm volatile("bar.sync 1, 224;" ::: "memory");

    // ---- top-2 + softmax, one thread per token ----
    if (tid < M_CTA && tok0 + tid < n_tokens) {
        const float* row = &lg[tid * LGS];
        const float* bs  = reinterpret_cast<const float*>(smem);
        float v1 = -3.402823466e+38f, v2 = -3.402823466e+38f;
        int i1 = 0, i2 = 0;
#pragma unroll
        for (int e = 0; e < NEXP; e++) {
            float v = row[e] + bs[e];
            if (v > v1)      { v2 = v1; i2 = i1; v1 = v; i1 = e; }
            else if (v > v2) { v2 = v;  i2 = e; }
        }
        float e2  = expf(v2 - v1);
        float inv = 1.0f / (1.0f + e2);
        const int g = tok0 + tid;
        out[2 * g + 0] = inv;
        out[2 * g + 1] = e2 * inv;
        out[2 * n_tokens + 2 * g + 0] = (float)i1;
        out[2 * n_tokens + 2 * g + 1] = (float)i2;
    }
}

// ---------------- launch ----------------
extern "C" void kernel_launch(void* const* d_in, const int* in_sizes, int n_in,
                              void* d_out, int out_size)
{
    const float* x = (const float*)d_in[0];
    const float* W = (const float*)d_in[1];
    const float* b = (const float*)d_in[2];
    float* out = (float*)d_out;

    const int n_tokens = in_sizes[0] / D_DIM;            // 16384
    const int grid = (n_tokens + M_CTA - 1) / M_CTA;     // 147

    cudaFuncSetAttribute(router_main, cudaFuncAttributeMaxDynamicSharedMemorySize, SMEM_TOTAL);

    wconv<<<NEXP * D_DIM / 256, 256>>>(W);
    router_main<<<grid, NTHREADS, SMEM_TOTAL>>>(x, b, out, n_tokens);
}